// round 14
// baseline (speedup 1.0000x reference)
#include <cuda_runtime.h>
#include <cuda_bf16.h>
#include <cstdint>

// ---------------------------------------------------------------------------
// 3-layer GRU + linear head. B=64, T=512, F=128, H=512, 3H=1536, O=128.
// GEMMs: bf16 split-precision mma + register double-buffering.
// Scan: tensor-core dot, k-split 8 x n-split 2 (halved reduction fan).
// ---------------------------------------------------------------------------
#define B_SZ   64
#define T_SZ   512
#define F_SZ   128
#define H_SZ   512
#define G3_SZ  1536
#define O_SZ   128
#define M_SZ   (B_SZ * T_SZ)

#define SCAN_NBLK  128

typedef unsigned long long u64;
typedef unsigned int u32;

__device__ __forceinline__ unsigned ld_acq(const unsigned* p) {
    unsigned v; asm volatile("ld.global.acquire.gpu.u32 %0, [%1];" : "=r"(v) : "l"(p) : "memory"); return v;
}
__device__ __forceinline__ void st_rel(unsigned* p, unsigned v) {
    asm volatile("st.global.release.gpu.u32 [%0], %1;" :: "l"(p), "r"(v) : "memory");
}

// ---------------------------------------------------------------------------
// Scratch (device globals -- allocation-free per harness rules)
// ---------------------------------------------------------------------------
__device__ float    g_xp[(size_t)M_SZ * G3_SZ];
__device__ float    g_hseq[(size_t)M_SZ * H_SZ];
__device__ u32      g_hbf[4][T_SZ][8192];     // frag-ordered bf16 hi/lo h
__device__ unsigned g_flags[4][32];
__device__ unsigned g_genf[4][32];

// ===========================================================================
// Shared mma helpers (conventions validated in R12/R13)
// ===========================================================================
__device__ __forceinline__ void mma_bf16(float* d, const u32* a, const u32* b) {
    asm volatile(
        "mma.sync.aligned.m16n8k16.row.col.f32.bf16.bf16.f32 "
        "{%0,%1,%2,%3}, {%4,%5,%6,%7}, {%8,%9}, {%0,%1,%2,%3};"
        : "+f"(d[0]), "+f"(d[1]), "+f"(d[2]), "+f"(d[3])
        : "r"(a[0]), "r"(a[1]), "r"(a[2]), "r"(a[3]), "r"(b[0]), "r"(b[1]));
}
__device__ __forceinline__ u32 pack_bf2(__nv_bfloat16 lo16, __nv_bfloat16 hi16) {
    __nv_bfloat162 t; t.x = lo16; t.y = hi16;   // .x = low half = first k
    return *(u32*)&t;
}
__device__ __forceinline__ void split_bf(float x, __nv_bfloat16& h, __nv_bfloat16& l) {
    h = __float2bfloat16_rn(x);
    l = __float2bfloat16_rn(x - __bfloat162float(h));
}

// ===========================================================================
// bf16 split-precision tensor GEMM + register double-buffered gmem loads.
// ===========================================================================
#define AP 40

__global__ void __launch_bounds__(256)
tgemm_kernel(const float* __restrict__ A, const float* __restrict__ W,
             const float* __restrict__ bias, float* __restrict__ C,
             int M, int N, int K)
{
    __shared__ __align__(16) unsigned short Ahi[128 * AP];
    __shared__ __align__(16) unsigned short Alo[128 * AP];
    __shared__ __align__(16) unsigned short Whi[128 * AP];
    __shared__ __align__(16) unsigned short Wlo[128 * AP];

    const int tid  = threadIdx.x;
    const int wid  = tid >> 5;
    const int lane = tid & 31;
    const int n0   = blockIdx.x * 128;
    const int m0   = blockIdx.y * 128;

    const int wm = wid & 1;
    const int wn = wid >> 1;
    const int qrow = lane >> 2;
    const int qk   = lane & 3;

    float acc[4][4][4];
#pragma unroll
    for (int i = 0; i < 4; i++)
#pragma unroll
        for (int j = 0; j < 4; j++)
#pragma unroll
            for (int c = 0; c < 4; c++) acc[i][j][c] = 0.f;

    const int srow = tid >> 1;
    const int scol = (tid & 1) * 16;

    const int nchunk = K >> 5;

    float4 pav[4], pwv[4];
#pragma unroll
    for (int q = 0; q < 4; q++) {
        const int col = scol + q * 4;
        pav[q] = *(const float4*)(A + (size_t)(m0 + srow) * K + col);
        pwv[q] = *(const float4*)(W + (size_t)(n0 + srow) * K + col);
    }

    for (int kc = 0; kc < nchunk; kc++) {
        // ---- split staged registers to smem
#pragma unroll
        for (int q = 0; q < 4; q++) {
            const int col = scol + q * 4;
            __nv_bfloat16 h0, l0, h1, l1, h2, l2, h3, l3;
            split_bf(pav[q].x, h0, l0); split_bf(pav[q].y, h1, l1);
            split_bf(pav[q].z, h2, l2); split_bf(pav[q].w, h3, l3);
            *(u32*)&Ahi[srow * AP + col]     = pack_bf2(h0, h1);
            *(u32*)&Ahi[srow * AP + col + 2] = pack_bf2(h2, h3);
            *(u32*)&Alo[srow * AP + col]     = pack_bf2(l0, l1);
            *(u32*)&Alo[srow * AP + col + 2] = pack_bf2(l2, l3);

            split_bf(pwv[q].x, h0, l0); split_bf(pwv[q].y, h1, l1);
            split_bf(pwv[q].z, h2, l2); split_bf(pwv[q].w, h3, l3);
            *(u32*)&Whi[srow * AP + col]     = pack_bf2(h0, h1);
            *(u32*)&Whi[srow * AP + col + 2] = pack_bf2(h2, h3);
            *(u32*)&Wlo[srow * AP + col]     = pack_bf2(l0, l1);
            *(u32*)&Wlo[srow * AP + col + 2] = pack_bf2(l2, l3);
        }
        __syncthreads();

        // ---- prefetch next chunk (overlaps MMA below)
        if (kc + 1 < nchunk) {
#pragma unroll
            for (int q = 0; q < 4; q++) {
                const int col = (kc + 1) * 32 + scol + q * 4;
                pav[q] = *(const float4*)(A + (size_t)(m0 + srow) * K + col);
                pwv[q] = *(const float4*)(W + (size_t)(n0 + srow) * K + col);
            }
        }

#pragma unroll
        for (int ks = 0; ks < 2; ks++) {
            const int k16 = ks * 16;
            u32 afh[4][4], afl[4][4];
            u32 bfh[4][2], bfl[4][2];
#pragma unroll
            for (int mt = 0; mt < 4; mt++) {
                const int r0 = (wm * 64 + mt * 16 + qrow) * AP + k16 + qk * 2;
                afh[mt][0] = *(const u32*)&Ahi[r0];
                afh[mt][1] = *(const u32*)&Ahi[r0 + 8 * AP];
                afh[mt][2] = *(const u32*)&Ahi[r0 + 8];
                afh[mt][3] = *(const u32*)&Ahi[r0 + 8 * AP + 8];
                afl[mt][0] = *(const u32*)&Alo[r0];
                afl[mt][1] = *(const u32*)&Alo[r0 + 8 * AP];
                afl[mt][2] = *(const u32*)&Alo[r0 + 8];
                afl[mt][3] = *(const u32*)&Alo[r0 + 8 * AP + 8];
            }
#pragma unroll
            for (int nt = 0; nt < 4; nt++) {
                const int r0 = (wn * 32 + nt * 8 + qrow) * AP + k16 + qk * 2;
                bfh[nt][0] = *(const u32*)&Whi[r0];
                bfh[nt][1] = *(const u32*)&Whi[r0 + 8];
                bfl[nt][0] = *(const u32*)&Wlo[r0];
                bfl[nt][1] = *(const u32*)&Wlo[r0 + 8];
            }
#pragma unroll
            for (int mt = 0; mt < 4; mt++)
#pragma unroll
                for (int nt = 0; nt < 4; nt++) {
                    mma_bf16(acc[mt][nt], afh[mt], bfh[nt]);
                    mma_bf16(acc[mt][nt], afh[mt], bfl[nt]);
                    mma_bf16(acc[mt][nt], afl[mt], bfh[nt]);
                }
        }
        __syncthreads();
    }

#pragma unroll
    for (int mt = 0; mt < 4; mt++) {
        const int mrow = m0 + wm * 64 + mt * 16 + qrow;
#pragma unroll
        for (int nt = 0; nt < 4; nt++) {
            const int ncol = n0 + wn * 32 + nt * 8 + qk * 2;
            const float b0 = bias[ncol], b1 = bias[ncol + 1];
            float2 v0 = make_float2(acc[mt][nt][0] + b0, acc[mt][nt][1] + b1);
            float2 v1 = make_float2(acc[mt][nt][2] + b0, acc[mt][nt][3] + b1);
            *(float2*)(C + (size_t)mrow * N + ncol)       = v0;
            *(float2*)(C + (size_t)(mrow + 8) * N + ncol) = v1;
        }
    }
}

// ===========================================================================
// Persistent GRU scan with tensor-core dot, k8 x n2 warp split.
// 128 blocks = 4 batch-groups x 32 j-tiles, 512 threads = 16 warps.
// Warp (kh = ks&7, nh = ks>>3): chunks 4kh..4kh+3, n-tiles 3nh..3nh+2
// -> 36 mma/warp; each output summed over 8 kh-warps (was 16).
// Weights pre-built as B-fragments (bf16 hi/lo) in smem; h flows as
// frag-ordered bf16 A-fragments via g_hbf; fp32 state in finalizer regs.
// Barrier: R5 two-hop.
// ===========================================================================
struct ScanSmem {
    u32      bfrag[2][32][6][32][2];   // [hl][chunk][ntile][lane][2]  98304 B
    u32      afrag[2 * 32 * 32 * 4];   // [hl][chunk][lane][4]         32768 B
    float    red[512][14];             // 12 partials, pitch 14        28672 B
    float    bhs[48];
    unsigned baseu[2];
};

__global__ void __launch_bounds__(512, 1)
scan_kernel(const float* __restrict__ Whh, const float* __restrict__ bhh,
            const float* __restrict__ xp, float* __restrict__ hseq)
{
    extern __shared__ ScanSmem smem[];
    ScanSmem& s = smem[0];

    const int tid  = threadIdx.x;
    const int lane = tid & 31;
    const int ks   = tid >> 5;          // warp id
    const int kh   = ks & 7;            // k-half: chunks 4kh..4kh+3
    const int nh   = ks >> 3;           // n-half: ntiles 3nh..3nh+2
    const int bt   = blockIdx.x >> 5;
    const int jt   = blockIdx.x & 31;
    const int b0   = bt * 16;
    const int j0   = jt * 16;

    if (tid == 0) {
        s.baseu[0] = ld_acq(&g_flags[bt][jt]);
        s.baseu[1] = ld_acq(&g_genf[bt][0]);
    }

    // ---- preamble: build B fragments from Whh (once)
    for (int i = tid; i < 32 * 6 * 32; i += 512) {
        const int ln = i & 31;
        const int n  = (i >> 5) % 6;
        const int c  = i / (6 * 32);
        const int g  = n >> 1;
        const int jj = (n & 1) * 8 + (ln >> 2);
        const int k  = c * 16 + (ln & 3) * 2;
        const float* wrow = Whh + (size_t)(g * H_SZ + j0 + jj) * H_SZ + k;
        float2 w0 = *(const float2*)(wrow);
        float2 w1 = *(const float2*)(wrow + 8);
        __nv_bfloat16 h0, l0, h1, l1, h2, l2, h3, l3;
        split_bf(w0.x, h0, l0); split_bf(w0.y, h1, l1);
        split_bf(w1.x, h2, l2); split_bf(w1.y, h3, l3);
        s.bfrag[0][c][n][ln][0] = pack_bf2(h0, h1);
        s.bfrag[0][c][n][ln][1] = pack_bf2(h2, h3);
        s.bfrag[1][c][n][ln][0] = pack_bf2(l0, l1);
        s.bfrag[1][c][n][ln][1] = pack_bf2(l2, l3);
    }
    if (tid < 48) s.bhs[tid] = bhh[(tid >> 4) * H_SZ + j0 + (tid & 15)];
    __syncthreads();

    const unsigned base_flag = s.baseu[0];
    const unsigned base_gen  = s.baseu[1];

    // Finalizer identity (tid < 128): 1 batch x 2 j each.
    const int fb   = tid >> 5;
    const int fi5  = tid & 31;
    const int fbg  = fi5 >> 3;
    const int fjg  = fi5 & 7;
    const int fbl  = fbg * 4 + fb;
    const int fjl0 = fjg * 2;
    const int lane_c = (fbl & 7) * 4 + (fjg & 3);
    const int coff   = (fbl >= 8) ? 2 : 0;
    const int hbf_off = jt * 128 + lane_c * 4 + ((fbl >= 8) ? 1 : 0) + ((fjg >= 4) ? 2 : 0);

    float2 hvp = make_float2(0.f, 0.f);

    float2 xv[3];
    if (tid < 128) {
        const size_t row = ((size_t)(b0 + fbl) * T_SZ + 0) * G3_SZ;
#pragma unroll
        for (int g = 0; g < 3; g++)
            xv[g] = *(const float2*)(xp + row + g * H_SZ + j0 + fjl0);
    }

    for (int t = 0; t < T_SZ; t++) {
        // ---- stage A fragments (contiguous copy of frag-ordered g_hbf)
        if (t == 0) {
            const uint4 z = make_uint4(0u, 0u, 0u, 0u);
#pragma unroll
            for (int u = 0; u < 4; u++)
                *(uint4*)&s.afrag[u * 2048 + tid * 4] = z;
        } else {
            const u32* src = &g_hbf[bt][t - 1][0];
            uint4 v[4];
#pragma unroll
            for (int u = 0; u < 4; u++)
                v[u] = *(const uint4*)&src[u * 2048 + tid * 4];
#pragma unroll
            for (int u = 0; u < 4; u++)
                *(uint4*)&s.afrag[u * 2048 + tid * 4] = v[u];
        }
        __syncthreads();

        // ---- tensor dot: warp (kh, nh): 4 chunks x 3 ntiles x 3 products
        float dacc[3][4];
#pragma unroll
        for (int n = 0; n < 3; n++)
#pragma unroll
            for (int c = 0; c < 4; c++) dacc[n][c] = 0.f;

        {
#pragma unroll
            for (int cc = 0; cc < 4; cc++) {
                const int c = 4 * kh + cc;
                u32 ah[4], al[4];
                *(uint4*)ah = *(const uint4*)&s.afrag[(0 * 32 + c) * 128 + lane * 4];
                *(uint4*)al = *(const uint4*)&s.afrag[(1 * 32 + c) * 128 + lane * 4];
#pragma unroll
                for (int nl = 0; nl < 3; nl++) {
                    const int n = 3 * nh + nl;
                    u32 bh[2], bl[2];
                    bh[0] = s.bfrag[0][c][n][lane][0];
                    bh[1] = s.bfrag[0][c][n][lane][1];
                    bl[0] = s.bfrag[1][c][n][lane][0];
                    bl[1] = s.bfrag[1][c][n][lane][1];
                    mma_bf16(dacc[nl], ah, bh);
                    mma_bf16(dacc[nl], ah, bl);
                    mma_bf16(dacc[nl], al, bh);
                }
            }
        }

        // ---- write partials (6 STS.64, layout [nloc*4 + {0,2}])
        {
            float* rp = &s.red[tid][0];
#pragma unroll
            for (int nl = 0; nl < 3; nl++) {
                *(float2*)(rp + nl * 4)     = make_float2(dacc[nl][0], dacc[nl][1]);
                *(float2*)(rp + nl * 4 + 2) = make_float2(dacc[nl][2], dacc[nl][3]);
            }
        }
        __syncthreads();

        // ---- finalize: tid < 128; sum 8 kh-warps' fragments, gates, stores
        if (tid < 128) {
            float2 tg[3];
#pragma unroll
            for (int g = 0; g < 3; g++) {
                const int r   = g * 16 + fjl0;
                const int n   = r >> 3;               // global ntile 0..5
                const int nho = (n >= 3) ? 1 : 0;
                const int nl  = n - 3 * nho;
                const int slot = nl * 4 + coff;
                float2 sum = make_float2(0.f, 0.f);
#pragma unroll
                for (int w = 0; w < 8; w++) {
                    const int src = (nho * 8 + w) * 32 + lane_c;
                    float2 v = *(const float2*)&s.red[src][slot];
                    sum.x += v.x; sum.y += v.y;
                }
                tg[g] = sum;
            }
            float2 hv;
#pragma unroll
            for (int p = 0; p < 2; p++) {
                const int jl = fjl0 + p;
                float dr = (p == 0) ? tg[0].x : tg[0].y;
                float dz = (p == 0) ? tg[1].x : tg[1].y;
                float dn = (p == 0) ? tg[2].x : tg[2].y;
                float xr = (p == 0) ? xv[0].x : xv[0].y;
                float xz = (p == 0) ? xv[1].x : xv[1].y;
                float xn = (p == 0) ? xv[2].x : xv[2].y;
                float rg = 1.f / (1.f + __expf(-(xr + dr + s.bhs[jl])));
                float zg = 1.f / (1.f + __expf(-(xz + dz + s.bhs[16 + jl])));
                float ng = tanhf(xn + rg * (dn + s.bhs[32 + jl]));
                float hp = (p == 0) ? hvp.x : hvp.y;
                float h  = (1.f - zg) * ng + zg * hp;
                if (p == 0) hv.x = h; else hv.y = h;
            }
            hvp = hv;

            *(float2*)(hseq + ((size_t)(b0 + fbl) * T_SZ + t) * H_SZ + j0 + fjl0) = hv;
            __nv_bfloat16 xh, xl, yh, yl;
            split_bf(hv.x, xh, xl); split_bf(hv.y, yh, yl);
            u32* dst = &g_hbf[bt][t][0];
            dst[hbf_off]        = pack_bf2(xh, yh);
            dst[4096 + hbf_off] = pack_bf2(xl, yl);

            const int tn = (t + 1 < T_SZ) ? t + 1 : t;
            const size_t row = ((size_t)(b0 + fbl) * T_SZ + tn) * G3_SZ;
#pragma unroll
            for (int g = 0; g < 3; g++)
                xv[g] = *(const float2*)(xp + row + g * H_SZ + j0 + fjl0);
        }
        __syncthreads();

        // ---- two-hop group barrier (R5)
        {
            const unsigned tgt = base_flag + (unsigned)t + 1u;
            if (tid == 0) st_rel(&g_flags[bt][jt], tgt);
            if (jt == 0) {
                if (tid < 32) {
                    while ((int)(ld_acq(&g_flags[bt][tid]) - tgt) < 0) { }
                    __syncwarp();
                    if (tid == 0) st_rel(&g_genf[bt][0], base_gen + (unsigned)t + 1u);
                }
            } else if (tid == 0) {
                const unsigned gt = base_gen + (unsigned)t + 1u;
                while ((int)(ld_acq(&g_genf[bt][0]) - gt) < 0) { }
            }
        }
        __syncthreads();
    }
}

// ---------------------------------------------------------------------------
// Launch
// ---------------------------------------------------------------------------
extern "C" void kernel_launch(void* const* d_in, const int* in_sizes, int n_in,
                              void* d_out, int out_size)
{
    (void)in_sizes; (void)n_in; (void)out_size;
    const float* x    = (const float*)d_in[0];
    const float* Wih0 = (const float*)d_in[1];
    const float* Whh0 = (const float*)d_in[2];
    const float* bih0 = (const float*)d_in[3];
    const float* bhh0 = (const float*)d_in[4];
    const float* Wih1 = (const float*)d_in[5];
    const float* Whh1 = (const float*)d_in[6];
    const float* bih1 = (const float*)d_in[7];
    const float* bhh1 = (const float*)d_in[8];
    const float* Wih2 = (const float*)d_in[9];
    const float* Whh2 = (const float*)d_in[10];
    const float* bih2 = (const float*)d_in[11];
    const float* bhh2 = (const float*)d_in[12];
    const float* Wout = (const float*)d_in[13];
    const float* bout = (const float*)d_in[14];
    float* out = (float*)d_out;

    cudaFuncSetAttribute(scan_kernel, cudaFuncAttributeMaxDynamicSharedMemorySize,
                         (int)sizeof(ScanSmem));

    void *xp_v = nullptr, *hs_v = nullptr;
    cudaGetSymbolAddress(&xp_v, g_xp);
    cudaGetSymbolAddress(&hs_v, g_hseq);
    float* xpd = (float*)xp_v;
    float* hs  = (float*)hs_v;

    const dim3 tblk(256), sblk(512);
    const dim3 g_proj(G3_SZ / 128, M_SZ / 128);
    const dim3 g_head(O_SZ / 128,  M_SZ / 128);
    const size_t scan_smem = sizeof(ScanSmem);

    tgemm_kernel<<<g_proj, tblk>>>(x,  Wih0, bih0, xpd, M_SZ, G3_SZ, F_SZ);
    scan_kernel<<<SCAN_NBLK, sblk, scan_smem>>>(Whh0, bhh0, xpd, hs);
    tgemm_kernel<<<g_proj, tblk>>>(hs, Wih1, bih1, xpd, M_SZ, G3_SZ, H_SZ);
    scan_kernel<<<SCAN_NBLK, sblk, scan_smem>>>(Whh1, bhh1, xpd, hs);
    tgemm_kernel<<<g_proj, tblk>>>(hs, Wih2, bih2, xpd, M_SZ, G3_SZ, H_SZ);
    scan_kernel<<<SCAN_NBLK, sblk, scan_smem>>>(Whh2, bhh2, xpd, hs);
    tgemm_kernel<<<g_head, tblk>>>(hs, Wout, bout, out, M_SZ, O_SZ, H_SZ);
}